// round 14
// baseline (speedup 1.0000x reference)
#include <cuda_runtime.h>

constexpr int Nn = 4096;   // z rows
constexpr int Mm = 1024;   // e rows
constexpr int Dd = 64;     // feature dim

constexpr int NQ = 1024;                     // z-quarter per build block
constexpr int BK = 1024;                     // buckets per quarter
constexpr float LOb  = -6.0f;
constexpr float HIb  =  6.0f;
constexpr float INVW = BK / (HIb - LOb);

__device__ __forceinline__ int bucket_of(float v) {
    int k = (int)((v - LOb) * INVW);
    return min(max(k, 0), BK - 1);
}

// Scratch (no allocations allowed -> device globals)
__device__ __align__(16) float g_zt[Dd * Nn];    // z transposed: [D][N]
__device__ float g_pb[4 * Dd * Mm];              // per-query best, 4 z-quarters

// ---------------------------------------------------------------------------
// k1: ONE 32x32 z tile per block (shortest critical path — R7 config).
// Grid (2, 128), block (32,32): transpose into g_zt + mask + copy + zero loss.
__global__ void k1_prep(const float* __restrict__ z, const int* __restrict__ idx,
                        float* __restrict__ out) {
    __shared__ float tile[32][33];
    int bx = blockIdx.x, by = blockIdx.y;
    int tx = threadIdx.x, ty = threadIdx.y;

    int x = bx * 32 + tx;                // D index
    int y = by * 32 + ty;                // N index
    float v = z[y * Dd + x];
    tile[ty][tx] = v;

    int k = idx[y];
    out[1 + y * Dd + x]           = (x < k) ? v : 0.0f;   // z_masked
    out[1 + Nn * Dd + y * Dd + x] = v;                    // z_copy
    if (bx == 0 && by == 0 && tx == 0 && ty == 0) out[0] = 0.0f;

    __syncthreads();
    int ox = by * 32 + tx;               // N index (output inner)
    int oy = bx * 32 + ty;               // D index (output outer)
    g_zt[oy * Nn + ox] = tile[tx][ty];
}

// ---------------------------------------------------------------------------
// k2: grid 256 = 64 columns x 4 z-quarters, 2 blocks/SM (full occupancy).
// Block (d,h): bucket its 1024-value quarter (coalesced from g_zt), then
// thread t answers query m=t (direct gather from e, hidden under the build):
// scan own bucket + nearest nonempty bucket each side. Disjoint store to g_pb.
__global__ void __launch_bounds__(1024, 2) k2_nn(const float* __restrict__ e) {
    __shared__ float S[NQ];          // bucket-grouped quarter (4 KB)
    __shared__ int   cnt[BK];        // hist -> exclusive starts (4 KB)
    __shared__ int   wtot[32];

    const int bx = blockIdx.x;       // 0..255
    const int d  = bx & 63;
    const int h  = bx >> 6;          // which z-quarter
    const int t  = threadIdx.x;
    const int lane = t & 31, wid = t >> 5;

    // Prefetches: e gather (uncoalesced but L2-hot, overlapped by build) and
    // coalesced z quarter.
    float x = e[t * Dd + d];
    float v = g_zt[d * Nn + h * NQ + t];

    cnt[t] = 0;
    __syncthreads();

    // ---- histogram + within-bucket rank (1 ATOMS/thread) ----
    int b = bucket_of(v);
    int r = atomicAdd(&cnt[b], 1);
    __syncthreads();

    // ---- block exclusive scan, 1 bucket per thread ----
    int c = cnt[t];
    int inc = c;
    #pragma unroll
    for (int o = 1; o < 32; o <<= 1) {
        int n = __shfl_up_sync(0xFFFFFFFFu, inc, o);
        if (lane >= o) inc += n;
    }
    if (lane == 31) wtot[wid] = inc;
    __syncthreads();
    if (wid == 0) {
        int ws = wtot[lane];
        int wi = ws;
        #pragma unroll
        for (int o = 1; o < 32; o <<= 1) {
            int n = __shfl_up_sync(0xFFFFFFFFu, wi, o);
            if (lane >= o) wi += n;
        }
        wtot[lane] = wi - ws;            // exclusive warp offsets
    }
    __syncthreads();
    cnt[t] = (inc - c) + wtot[wid];      // exclusive start of bucket t
    __syncthreads();

    // ---- scatter: plain store (start + rank unique) ----
    S[cnt[b] + r] = v;
    __syncthreads();

    // ---- query: own bucket + nearest nonempty bucket each side ----
    int k0 = bucket_of(x);
    int start = cnt[k0];
    int end   = (k0 < BK - 1) ? cnt[k0 + 1] : NQ;

    float best = 1e30f;
    for (int j = start; j < end; j++)
        best = fminf(best, fabsf(S[j] - x));

    if (start > 0) {                     // nearest nonempty bucket below
        int bb = bucket_of(S[start - 1]);
        int lo = cnt[bb];                // its segment is [lo, start)
        for (int j = lo; j < start; j++)
            best = fminf(best, fabsf(S[j] - x));
    }
    if (end < NQ) {                      // nearest nonempty bucket above
        int bb = bucket_of(S[end]);
        int hi = (bb < BK - 1) ? cnt[bb + 1] : NQ;
        for (int j = end; j < hi; j++)
            best = fminf(best, fabsf(S[j] - x));
    }

    g_pb[h * (Dd * Mm) + d * Mm + t] = best;   // disjoint plain store
}

// ---------------------------------------------------------------------------
// k3: combine 4 quarters + reduce -> out[0] += sum(min^2) / 65536.
__global__ void __launch_bounds__(1024) k3_reduce(float* __restrict__ out) {
    __shared__ float red[32];
    int i = blockIdx.x * 1024 + threadIdx.x;
    float a = g_pb[i];
    float b = g_pb[Dd * Mm + i];
    float c = g_pb[2 * Dd * Mm + i];
    float d = g_pb[3 * Dd * Mm + i];
    float m = fminf(fminf(a, b), fminf(c, d));
    float val = m * m * (1.0f / (float)(Mm * Dd));
    const int lane = threadIdx.x & 31, wid = threadIdx.x >> 5;
    #pragma unroll
    for (int o = 16; o > 0; o >>= 1)
        val += __shfl_xor_sync(0xFFFFFFFFu, val, o);
    if (lane == 0) red[wid] = val;
    __syncthreads();
    if (wid == 0) {
        float sv = red[lane];
        #pragma unroll
        for (int o = 16; o > 0; o >>= 1)
            sv += __shfl_xor_sync(0xFFFFFFFFu, sv, o);
        if (lane == 0) atomicAdd(out, sv);
    }
}

// ---------------------------------------------------------------------------
extern "C" void kernel_launch(void* const* d_in, const int* in_sizes, int n_in,
                              void* d_out, int out_size) {
    const float* z = (const float*)d_in[0];
    const float* e = (const float*)d_in[1];
    const int* idx = (const int*)d_in[2];
    float* out = (float*)d_out;

    k1_prep<<<dim3(2, 128), dim3(32, 32)>>>(z, idx, out);
    k2_nn<<<256, 1024>>>(e);
    k3_reduce<<<64, 1024>>>(out);
}

// round 15
// speedup vs baseline: 1.2228x; 1.2228x over previous
#include <cuda_runtime.h>
#include <cooperative_groups.h>
namespace cg = cooperative_groups;

constexpr int Nn = 4096;   // z rows
constexpr int Mm = 1024;   // e rows
constexpr int Dd = 64;     // feature dim

constexpr int NH = 2048;                     // z-half per CTA
constexpr int BK = 2048;                     // buckets per half
constexpr float LOb  = -6.0f;
constexpr float HIb  =  6.0f;
constexpr float INVW = BK / (HIb - LOb);

__device__ __forceinline__ int bucket_of(float v) {
    int k = (int)((v - LOb) * INVW);
    return min(max(k, 0), BK - 1);
}

// Scratch (no allocations allowed -> device globals)
__device__ __align__(16) float g_zt[Dd * Nn];    // z transposed: [D][N]

// ---------------------------------------------------------------------------
// k1: ONE 32x32 z tile per block (R7's proven config).
// Grid (2, 128), block (32,32): transpose into g_zt + mask + copy + zero loss.
__global__ void k1_prep(const float* __restrict__ z, const int* __restrict__ idx,
                        float* __restrict__ out) {
    __shared__ float tile[32][33];
    int bx = blockIdx.x, by = blockIdx.y;
    int tx = threadIdx.x, ty = threadIdx.y;

    int x = bx * 32 + tx;                // D index
    int y = by * 32 + ty;                // N index
    float v = z[y * Dd + x];
    tile[ty][tx] = v;

    int k = idx[y];
    out[1 + y * Dd + x]           = (x < k) ? v : 0.0f;   // z_masked
    out[1 + Nn * Dd + y * Dd + x] = v;                    // z_copy
    if (bx == 0 && by == 0 && tx == 0 && ty == 0) out[0] = 0.0f;

    __syncthreads();
    int ox = by * 32 + tx;               // N index (output inner)
    int oy = bx * 32 + ty;               // D index (output outer)
    g_zt[oy * Nn + ox] = tile[tx][ty];
}

// ---------------------------------------------------------------------------
// k2: 128 CTAs = 64 clusters of 2. CTA (d,h) builds half-column h of column d
// (bucket grouping, single atomic pass) and answers all 1024 queries into
// sbest[]. Cluster combine: rank 0 reads peer sbest via DSMEM, mins, squares,
// block-reduces, one atomicAdd into out[0]. No third kernel, no global pb.
__global__ void __cluster_dims__(2, 1, 1) __launch_bounds__(1024, 1)
k2_nn(const float* __restrict__ e, float* __restrict__ out) {
    __shared__ float S[NH];          // bucket-grouped half-column (8 KB)
    __shared__ int   cnt[BK];        // hist -> exclusive starts (8 KB)
    __shared__ float sbest[Mm];      // per-query best for this half (4 KB)
    __shared__ int   wtot[32];
    __shared__ float red[32];

    const int bx = blockIdx.x;       // 0..127
    const int d  = bx >> 1;
    const int h  = bx & 1;           // cluster rank == z-half
    const int t  = threadIdx.x;
    const int lane = t & 31, wid = t >> 5;

    // Prefetch query (gather; overlapped by build) + z half (one LDG.64).
    float x = e[t * Dd + d];
    float2 vv = reinterpret_cast<const float2*>(g_zt + d * Nn + h * NH)[t];

    cnt[t] = 0; cnt[t + 1024] = 0;
    __syncthreads();

    // ---- single atomic pass: histogram + within-bucket rank ----
    int b0 = bucket_of(vv.x), b1 = bucket_of(vv.y);
    int r0 = atomicAdd(&cnt[b0], 1);
    int r1 = atomicAdd(&cnt[b1], 1);
    __syncthreads();

    // ---- block exclusive scan (2 buckets per thread) ----
    int c0 = cnt[2 * t], c1 = cnt[2 * t + 1];
    int s = c0 + c1;
    int inc = s;
    #pragma unroll
    for (int o = 1; o < 32; o <<= 1) {
        int n = __shfl_up_sync(0xFFFFFFFFu, inc, o);
        if (lane >= o) inc += n;
    }
    if (lane == 31) wtot[wid] = inc;
    __syncthreads();
    if (wid == 0) {
        int ws = wtot[lane];
        int wi = ws;
        #pragma unroll
        for (int o = 1; o < 32; o <<= 1) {
            int n = __shfl_up_sync(0xFFFFFFFFu, wi, o);
            if (lane >= o) wi += n;
        }
        wtot[lane] = wi - ws;            // exclusive warp offsets
    }
    __syncthreads();
    int excl = (inc - s) + wtot[wid];
    cnt[2 * t]     = excl;
    cnt[2 * t + 1] = excl + c0;
    __syncthreads();

    // ---- scatter: plain stores (start + rank unique) ----
    S[cnt[b0] + r0] = vv.x;
    S[cnt[b1] + r1] = vv.y;
    __syncthreads();

    // ---- query: own bucket + nearest nonempty bucket each side ----
    int k0 = bucket_of(x);
    int start = cnt[k0];
    int end   = (k0 < BK - 1) ? cnt[k0 + 1] : NH;

    float best = 1e30f;
    for (int j = start; j < end; j++)
        best = fminf(best, fabsf(S[j] - x));

    if (start > 0) {                     // nearest nonempty bucket below
        int bb = bucket_of(S[start - 1]);
        int lo = cnt[bb];                // its segment is [lo, start)
        for (int j = lo; j < start; j++)
            best = fminf(best, fabsf(S[j] - x));
    }
    if (end < NH) {                      // nearest nonempty bucket above
        int bb = bucket_of(S[end]);
        int hi = (bb < BK - 1) ? cnt[bb + 1] : NH;
        for (int j = end; j < hi; j++)
            best = fminf(best, fabsf(S[j] - x));
    }

    sbest[t] = best;

    // ---- cluster combine ----
    cg::cluster_group cluster = cg::this_cluster();
    cluster.sync();                      // both halves' sbest ready

    if (h == 0) {
        const float* peer = cluster.map_shared_rank(sbest, 1);
        float m = fminf(sbest[t], peer[t]);
        float val = m * m * (1.0f / (float)(Mm * Dd));
        #pragma unroll
        for (int o = 16; o > 0; o >>= 1)
            val += __shfl_xor_sync(0xFFFFFFFFu, val, o);
        if (lane == 0) red[wid] = val;
        __syncthreads();
        if (wid == 0) {
            float sv = red[lane];
            #pragma unroll
            for (int o = 16; o > 0; o >>= 1)
                sv += __shfl_xor_sync(0xFFFFFFFFu, sv, o);
            if (lane == 0) atomicAdd(out, sv);
        }
    }

    cluster.sync();                      // keep rank 1's smem alive until read
}

// ---------------------------------------------------------------------------
extern "C" void kernel_launch(void* const* d_in, const int* in_sizes, int n_in,
                              void* d_out, int out_size) {
    const float* z = (const float*)d_in[0];
    const float* e = (const float*)d_in[1];
    const int* idx = (const int*)d_in[2];
    float* out = (float*)d_out;

    k1_prep<<<dim3(2, 128), dim3(32, 32)>>>(z, idx, out);
    k2_nn<<<128, 1024>>>(e, out);
}